// round 4
// baseline (speedup 1.0000x reference)
#include <cuda_runtime.h>
#include <cstdint>

// Problem shape (fixed by the dataset): N=50000 nodes, E=800000 edges, D=256.
#define DIM   256
#define MAXN  50176
#define MAXE  802816

// -------- scratch (static device globals: no runtime allocation) --------
__device__ int   g_deg[MAXN];
__device__ int   g_off[MAXN + 1];
__device__ int   g_cur[MAXN];
__device__ int   g_eidx[MAXE];
__device__ float g_agg[(size_t)MAXN * DIM];

// -------- 1. zero degree counters --------
__global__ void k_zero_deg(int N) {
    int i = blockIdx.x * blockDim.x + threadIdx.x;
    if (i < N) g_deg[i] = 0;
}

// -------- 2. histogram of dst --------
__global__ void k_hist(const int* __restrict__ dst, int E) {
    int e = blockIdx.x * blockDim.x + threadIdx.x;
    if (e < E) atomicAdd(&g_deg[dst[e]], 1);
}

// -------- 3. single-block exclusive scan (shuffle-based) + cursor copy --------
__global__ void k_scan(int N) {
    __shared__ int warp_sums[32];
    __shared__ int s_carry;
    const int tid  = threadIdx.x;           // 1024 threads
    const int lane = tid & 31;
    const int warp = tid >> 5;

    if (tid == 0) s_carry = 0;
    __syncthreads();

    for (int base = 0; base < N; base += 1024) {
        int i = base + tid;
        int v = (i < N) ? g_deg[i] : 0;

        // inclusive warp scan
        int x = v;
        #pragma unroll
        for (int d = 1; d < 32; d <<= 1) {
            int y = __shfl_up_sync(0xffffffffu, x, d);
            if (lane >= d) x += y;
        }
        if (lane == 31) warp_sums[warp] = x;
        __syncthreads();
        if (warp == 0) {
            int ws = warp_sums[lane];
            #pragma unroll
            for (int d = 1; d < 32; d <<= 1) {
                int y = __shfl_up_sync(0xffffffffu, ws, d);
                if (lane >= d) ws += y;
            }
            warp_sums[lane] = ws;
        }
        __syncthreads();

        int warp_off = (warp == 0) ? 0 : warp_sums[warp - 1];
        int incl = x + warp_off + s_carry;   // inclusive over all processed so far
        int excl = incl - v;
        if (i < N) g_off[i] = excl;

        __syncthreads();                      // everyone has read s_carry
        if (tid == 1023) s_carry = incl;      // tail thread: v=0 if OOB -> total
        __syncthreads();
    }
    if (tid == 0) g_off[N] = s_carry;
    __syncthreads();

    // copy offsets -> cursors for the bucket pass
    for (int i = tid; i < N; i += 1024) g_cur[i] = g_off[i];
}

// -------- 4. bucket edge ids by dst --------
__global__ void k_bucket(const int* __restrict__ dst, int E) {
    int e = blockIdx.x * blockDim.x + threadIdx.x;
    if (e < E) {
        int pos = atomicAdd(&g_cur[dst[e]], 1);
        g_eidx[pos] = e;
    }
}

// -------- 5. per-node aggregation: agg[n] = sum_{e in bucket(n)} e_w[e] * h[src[e]] --------
// one block per node, 256 threads = one feature each. No atomics on feature data;
// h (51 MB) is L2-resident, so the gathers are L2-bandwidth work.
#define AGG_CHUNK 64
__global__ void k_agg(const float* __restrict__ h,
                      const float* __restrict__ e_w,
                      const int*   __restrict__ src) {
    const int n = blockIdx.x;
    const int t = threadIdx.x;
    const int beg = g_off[n];
    const int end = g_off[n + 1];

    __shared__ int   s_src[AGG_CHUNK];
    __shared__ float s_w[AGG_CHUNK];

    float acc = 0.0f;
    for (int base = beg; base < end; base += AGG_CHUNK) {
        int cnt = end - base;
        if (cnt > AGG_CHUNK) cnt = AGG_CHUNK;
        if (t < cnt) {
            int eid  = g_eidx[base + t];
            s_src[t] = src[eid];
            s_w[t]   = e_w[eid];
        }
        __syncthreads();
        #pragma unroll 4
        for (int i = 0; i < cnt; i++) {
            acc = fmaf(__ldg(&h[(size_t)s_src[i] * DIM + t]), s_w[i], acc);
        }
        __syncthreads();
    }
    g_agg[(size_t)n * DIM + t] = acc;
}

// -------- 6. GEMM: out[M,256] = agg[M,256] @ W[256,256] + bias --------
// 64x64 tile, BK=16, 256 threads, 4x4 microtile per thread, fp32.
#define BM 64
#define BN 64
#define BK 16
__global__ void k_gemm(const float* __restrict__ B,     // weight [256,256]
                       const float* __restrict__ bias,  // [256]
                       float* __restrict__ C, int M) {
    __shared__ float As[BM][BK];        // [m][k]
    __shared__ float Bs[BK][BN];        // [k][n]

    const int tid = threadIdx.x;        // 256
    const int tx  = tid & 15;           // 0..15 -> n
    const int ty  = tid >> 4;           // 0..15 -> m
    const int tile_m = blockIdx.y * BM;
    const int tile_n = blockIdx.x * BN;
    const float* A = g_agg;

    float c[4][4] = {};

    for (int k0 = 0; k0 < DIM; k0 += BK) {
        // load A tile: 64x16 = 1024 elems, 4 per thread. idx -> (m = idx/16, k = idx%16)
        #pragma unroll
        for (int i = 0; i < 4; i++) {
            int idx = tid + i * 256;
            int m = idx >> 4;
            int k = idx & 15;
            int gm = tile_m + m;
            As[m][k] = (gm < M) ? A[(size_t)gm * DIM + k0 + k] : 0.0f;
        }
        // load B tile: 16x64, idx -> (k = idx/64, n = idx%64), fully coalesced
        #pragma unroll
        for (int i = 0; i < 4; i++) {
            int idx = tid + i * 256;
            int k = idx >> 6;
            int n = idx & 63;
            Bs[k][n] = B[(size_t)(k0 + k) * DIM + tile_n + n];
        }
        __syncthreads();

        #pragma unroll
        for (int k = 0; k < BK; k++) {
            float a0 = As[ty * 4 + 0][k];
            float a1 = As[ty * 4 + 1][k];
            float a2 = As[ty * 4 + 2][k];
            float a3 = As[ty * 4 + 3][k];
            float4 b = *reinterpret_cast<const float4*>(&Bs[k][tx * 4]);
            c[0][0] = fmaf(a0, b.x, c[0][0]); c[0][1] = fmaf(a0, b.y, c[0][1]);
            c[0][2] = fmaf(a0, b.z, c[0][2]); c[0][3] = fmaf(a0, b.w, c[0][3]);
            c[1][0] = fmaf(a1, b.x, c[1][0]); c[1][1] = fmaf(a1, b.y, c[1][1]);
            c[1][2] = fmaf(a1, b.z, c[1][2]); c[1][3] = fmaf(a1, b.w, c[1][3]);
            c[2][0] = fmaf(a2, b.x, c[2][0]); c[2][1] = fmaf(a2, b.y, c[2][1]);
            c[2][2] = fmaf(a2, b.z, c[2][2]); c[2][3] = fmaf(a2, b.w, c[2][3]);
            c[3][0] = fmaf(a3, b.x, c[3][0]); c[3][1] = fmaf(a3, b.y, c[3][1]);
            c[3][2] = fmaf(a3, b.z, c[3][2]); c[3][3] = fmaf(a3, b.w, c[3][3]);
        }
        __syncthreads();
    }

    #pragma unroll
    for (int i = 0; i < 4; i++) {
        int gm = tile_m + ty * 4 + i;
        if (gm >= M) continue;
        int gn = tile_n + tx * 4;
        float4 out;
        out.x = c[i][0] + bias[gn + 0];
        out.y = c[i][1] + bias[gn + 1];
        out.z = c[i][2] + bias[gn + 2];
        out.w = c[i][3] + bias[gn + 3];
        *reinterpret_cast<float4*>(&C[(size_t)gm * DIM + gn]) = out;
    }
}

extern "C" void kernel_launch(void* const* d_in, const int* in_sizes, int n_in,
                              void* d_out, int out_size) {
    const float* h      = (const float*)d_in[0];   // [N, 256]
    const float* e_w    = (const float*)d_in[1];   // [E, 1]
    const int*   src    = (const int*)  d_in[2];   // [E]
    const int*   dst    = (const int*)  d_in[3];   // [E]
    const float* weight = (const float*)d_in[4];   // [256, 256]
    const float* bias   = (const float*)d_in[5];   // [256]
    float* out = (float*)d_out;                    // [N, 256]

    const int N = in_sizes[0] / DIM;
    const int E = in_sizes[2];

    k_zero_deg<<<(N + 255) / 256, 256>>>(N);
    k_hist<<<(E + 255) / 256, 256>>>(dst, E);
    k_scan<<<1, 1024>>>(N);
    k_bucket<<<(E + 255) / 256, 256>>>(dst, E);
    k_agg<<<N, DIM>>>(h, e_w, src);

    dim3 gemm_grid(DIM / BN, (N + BM - 1) / BM);
    k_gemm<<<gemm_grid, 256>>>(weight, bias, out, N);
}